// round 4
// baseline (speedup 1.0000x reference)
#include <cuda_runtime.h>
#include <cuda_fp16.h>
#include <cstdint>

// ===========================================================================
// SNN (20 steps, 2 fused Linear+LIF layers + feedback) on mma.sync (HMMA).
// Spikes stored as exactly 2^-11, weights split into 2 fp16 limbs scaled by
// 2^11 -> products exact, residual ~|w|*2^-24 (fp32-equivalent trajectory).
// Round 4: steady-state kernel rebuilt as 128x256 CTA / 64x64 warp tile,
// 256-reg budget, single sync per chunk.
// ===========================================================================

#define BATCH   4096
#define DIM_D   1024
#define DIM_H1  2048
#define DIM_H2  1024
#define DIM_C   64
#define NUM_STEPS 20
#define BETA 0.9f
#define THRV 1.0f

// ---------------------------------------------------------------------------
// Device-global state / scratch
// ---------------------------------------------------------------------------
__device__ float  g_m1 [(size_t)BATCH * DIM_H1];
__device__ float  g_m2 [(size_t)BATCH * DIM_H2];
__device__ float  g_spk[(size_t)BATCH * DIM_H2];
__device__ __half g_s1 [(size_t)BATCH * DIM_H1];
__device__ __half g_s2 [(size_t)BATCH * DIM_H2];
__device__ __half g_w1h [(size_t)DIM_H1 * DIM_D];   // W1 * 2^11, hi limb
__device__ __half g_w1l [(size_t)DIM_H1 * DIM_D];   // W1 * 2^11, lo limb
__device__ __half g_w1hu[(size_t)DIM_H1 * DIM_D];   // W1 hi limb, unscaled (t=0)
__device__ __half g_w2h [(size_t)DIM_H2 * DIM_H1];
__device__ __half g_w2l [(size_t)DIM_H2 * DIM_H1];
__device__ __half g_xh  [(size_t)BATCH * DIM_D];
__device__ __half g_xl  [(size_t)BATCH * DIM_D];
__device__ __half g_xhs [(size_t)BATCH * DIM_D];

// ---------------------------------------------------------------------------
// PTX helpers (sm_80-era: compile clean for plain sm_100)
// ---------------------------------------------------------------------------
__device__ __forceinline__ uint32_t smem_u32(const void* p) {
    uint32_t a;
    asm("{ .reg .u64 t; cvta.to.shared.u64 t, %1; cvt.u32.u64 %0, t; }"
        : "=r"(a) : "l"(p));
    return a;
}
__device__ __forceinline__ void cp16(uint32_t dst, const void* src) {
    asm volatile("cp.async.cg.shared.global [%0], [%1], 16;"
                 :: "r"(dst), "l"(__cvta_generic_to_global(src)) : "memory");
}
__device__ __forceinline__ void ldsm4(uint32_t addr, uint32_t& r0, uint32_t& r1,
                                      uint32_t& r2, uint32_t& r3) {
    asm volatile("ldmatrix.sync.aligned.m8n8.x4.shared.b16 {%0,%1,%2,%3}, [%4];"
                 : "=r"(r0), "=r"(r1), "=r"(r2), "=r"(r3) : "r"(addr));
}
__device__ __forceinline__ void mma16816(float* c, const uint32_t a[4],
                                         uint32_t b0, uint32_t b1) {
    asm volatile(
        "mma.sync.aligned.m16n8k16.row.col.f32.f16.f16.f32 "
        "{%0,%1,%2,%3}, {%4,%5,%6,%7}, {%8,%9}, {%0,%1,%2,%3};"
        : "+f"(c[0]), "+f"(c[1]), "+f"(c[2]), "+f"(c[3])
        : "r"(a[0]), "r"(a[1]), "r"(a[2]), "r"(a[3]), "r"(b0), "r"(b1));
}

// ===========================================================================
// Steady-state kernel: 128(M) x 256(N) CTA tile, 64x64 warp tile, BK=64.
// D[row,col] = sum_k A[row,k]*(W0[col,k]+W1[col,k]); A = spikes (2^-11),
// W limbs pre-scaled by 2^11. Fused LIF epilogue.
// ===========================================================================
template <bool FIRST, bool SUM>
__global__ void __launch_bounds__(256, 1)
snn_main(const __half* __restrict__ A, const __half* __restrict__ W0,
         const __half* __restrict__ W1, const float* __restrict__ bias,
         float* __restrict__ mem, __half* __restrict__ spk,
         float* __restrict__ spk_sum, int N, int K)
{
    constexpr int A_TILE = 128 * 128;        // 16 KB (128 rows x 128 B)
    constexpr int W_TILE = 256 * 128;        // 32 KB per limb
    constexpr int STAGE  = A_TILE + 2 * W_TILE;  // 80 KB
    extern __shared__ char smem[];
    const uint32_t sb = smem_u32(smem);

    const int tid = threadIdx.x, lane = tid & 31, wid = tid >> 5;
    const int wm = wid >> 2, wn = wid & 3;             // 2 x 4 warp grid
    const int brow = blockIdx.y * 128, bcol = blockIdx.x * 256;

    const __half* Ab  = A  + (size_t)brow * K;
    const __half* Wp[2] = { W0 + (size_t)bcol * K, W1 + (size_t)bcol * K };

    auto load_stage = [&](int st, int k0) {
        const uint32_t s0 = sb + st * STAGE;
        // A: 128 rows x 8 x 16B  (4 per thread)
        for (int q = tid; q < 1024; q += 256) {
            int r = q >> 3, c = q & 7;
            cp16(s0 + r * 128 + ((c ^ (r & 7)) << 4),
                 Ab + (size_t)r * K + k0 + c * 8);
        }
        // W limbs: 2 x 256 rows x 8 x 16B  (16 per thread)
#pragma unroll
        for (int l = 0; l < 2; l++) {
            const __half* g = Wp[l];
            const uint32_t d = s0 + A_TILE + l * W_TILE;
            for (int q = tid; q < 2048; q += 256) {
                int r = q >> 3, c = q & 7;
                cp16(d + r * 128 + ((c ^ (r & 7)) << 4),
                     g + (size_t)r * K + k0 + c * 8);
            }
        }
        asm volatile("cp.async.commit_group;" ::: "memory");
    };

    // ldmatrix lane geometry
    const int arow = (lane & 7) + 8 * ((lane >> 3) & 1);
    const int asel = lane >> 4;
    const int brw  = (lane & 7) + 8 * (lane >> 4);
    const int bsel = (lane >> 3) & 1;
    const int sx   = lane & 7;

    float acc[4][8][4];
#pragma unroll
    for (int i = 0; i < 4; i++)
#pragma unroll
        for (int j = 0; j < 8; j++)
#pragma unroll
            for (int k = 0; k < 4; k++) acc[i][j][k] = 0.0f;

    const int nch = K / 64;
    load_stage(0, 0);

    for (int ch = 0; ch < nch; ch++) {
        asm volatile("cp.async.wait_group 0;" ::: "memory");
        __syncthreads();
        if (ch + 1 < nch) load_stage((ch + 1) & 1, (ch + 1) * 64);

        const uint32_t s0 = sb + (ch & 1) * STAGE;
        const uint32_t a_base = s0 + (wm * 64 + arow) * 128;
        const uint32_t b_base0 = s0 + A_TILE + (wn * 64 + brw) * 128;

#pragma unroll
        for (int ks = 0; ks < 4; ks++) {
            const uint32_t aoff = ((2 * ks + asel) ^ sx) << 4;
            const uint32_t boff = ((2 * ks + bsel) ^ sx) << 4;
            uint32_t a[4][4];
#pragma unroll
            for (int mf = 0; mf < 4; mf++)
                ldsm4(a_base + mf * 16 * 128 + aoff,
                      a[mf][0], a[mf][1], a[mf][2], a[mf][3]);
#pragma unroll
            for (int w = 0; w < 2; w++) {
                uint32_t b[16];
                const uint32_t bw = b_base0 + w * W_TILE + boff;
#pragma unroll
                for (int h = 0; h < 4; h++)
                    ldsm4(bw + h * 16 * 128, b[4 * h], b[4 * h + 1],
                          b[4 * h + 2], b[4 * h + 3]);
#pragma unroll
                for (int mf = 0; mf < 4; mf++)
#pragma unroll
                    for (int nf = 0; nf < 8; nf++)
                        mma16816(acc[mf][nf], a[mf], b[2 * nf], b[2 * nf + 1]);
            }
        }
    }

    // ---- Fused LIF epilogue on register accumulators ----
    const int qr = lane >> 2, qc = (lane & 3) * 2;
#pragma unroll
    for (int mf = 0; mf < 4; mf++)
#pragma unroll
    for (int h2 = 0; h2 < 2; h2++) {
        const int row = brow + wm * 64 + mf * 16 + qr + 8 * h2;
#pragma unroll
        for (int nf = 0; nf < 8; nf++) {
            const int col = bcol + wn * 64 + nf * 8 + qc;
            const size_t ix = (size_t)row * N + col;
            float2 bb = *reinterpret_cast<const float2*>(bias + col);
            float v0 = acc[mf][nf][2 * h2 + 0] + bb.x;
            float v1 = acc[mf][nf][2 * h2 + 1] + bb.y;
            float m0, m1v;
            if (FIRST) {
                m0 = v0; m1v = v1;
            } else {
                float2 mo = *reinterpret_cast<const float2*>(mem + ix);
                m0  = BETA * mo.x + v0 - ((mo.x > THRV) ? THRV : 0.0f);
                m1v = BETA * mo.y + v1 - ((mo.y > THRV) ? THRV : 0.0f);
            }
            const bool sp0 = m0 > THRV, sp1 = m1v > THRV;
            *reinterpret_cast<float2*>(mem + ix) = make_float2(m0, m1v);
            uint32_t sv = (sp0 ? 0x1000u : 0u) | (sp1 ? 0x10000000u : 0u);
            *reinterpret_cast<uint32_t*>(spk + ix) = sv;
            if (SUM) {
                float a0 = sp0 ? 1.0f : 0.0f, a1 = sp1 ? 1.0f : 0.0f;
                float2* ss = reinterpret_cast<float2*>(spk_sum + ix);
                if (FIRST) {
                    *ss = make_float2(a0, a1);
                } else {
                    float2 o = *ss;
                    *ss = make_float2(o.x + a0, o.y + a1);
                }
            }
        }
    }
}

// ===========================================================================
// t=0 layer-1 kernel (real-valued x, 3 limb products), 128x128 tile.
// Runs once; kept from round 3.
// ===========================================================================
__global__ void __launch_bounds__(256, 2)
snn_tz(const __half* __restrict__ A0, const __half* __restrict__ A1,
       const __half* __restrict__ A2,
       const __half* __restrict__ W0, const __half* __restrict__ W1,
       const float* __restrict__ bias, float* __restrict__ mem,
       __half* __restrict__ spk, int N, int K)
{
    constexpr int TILE = 16384;
    constexpr int STAGE = 5 * TILE;
    extern __shared__ char smem[];
    const uint32_t sb = smem_u32(smem);

    const int tid = threadIdx.x, lane = tid & 31, wid = tid >> 5;
    const int wm = wid >> 2, wn = wid & 3;
    const int brow = blockIdx.y * 128, bcol = blockIdx.x * 128;

    const __half* Ap[3] = { A0 + (size_t)brow * K, A1 + (size_t)brow * K,
                            A2 + (size_t)brow * K };
    const __half* Wp[2] = { W0 + (size_t)bcol * K, W1 + (size_t)bcol * K };

    auto load_stage = [&](int st, int k0) {
        const uint32_t s0 = sb + st * STAGE;
#pragma unroll
        for (int l = 0; l < 3; l++) {
            const uint32_t d = s0 + l * TILE;
            for (int q = tid; q < 1024; q += 256) {
                int r = q >> 3, c = q & 7;
                cp16(d + r * 128 + ((c ^ (r & 7)) << 4),
                     Ap[l] + (size_t)r * K + k0 + c * 8);
            }
        }
#pragma unroll
        for (int l = 0; l < 2; l++) {
            const uint32_t d = s0 + (3 + l) * TILE;
            for (int q = tid; q < 1024; q += 256) {
                int r = q >> 3, c = q & 7;
                cp16(d + r * 128 + ((c ^ (r & 7)) << 4),
                     Wp[l] + (size_t)r * K + k0 + c * 8);
            }
        }
        asm volatile("cp.async.commit_group;" ::: "memory");
    };

    const int arow = (lane & 7) + 8 * ((lane >> 3) & 1);
    const int asel = lane >> 4;
    const int brw  = (lane & 7) + 8 * (lane >> 4);
    const int bsel = (lane >> 3) & 1;
    const int sx   = lane & 7;

    float acc[4][4][4];
#pragma unroll
    for (int i = 0; i < 4; i++)
#pragma unroll
        for (int j = 0; j < 4; j++)
#pragma unroll
            for (int k = 0; k < 4; k++) acc[i][j][k] = 0.0f;

    const int nch = K / 64;
    load_stage(0, 0);

    for (int ch = 0; ch < nch; ch++) {
        asm volatile("cp.async.wait_group 0;" ::: "memory");
        __syncthreads();
        if (ch + 1 < nch) load_stage((ch + 1) & 1, (ch + 1) * 64);

        const uint32_t s0 = sb + (ch & 1) * STAGE;
#pragma unroll
        for (int ks = 0; ks < 4; ks++) {
            const uint32_t aoff = ((2 * ks + asel) ^ sx) << 4;
            const uint32_t boff = ((2 * ks + bsel) ^ sx) << 4;
            uint32_t b[2][8];
#pragma unroll
            for (int w = 0; w < 2; w++) {
                const uint32_t bw = s0 + (3 + w) * TILE + (wn * 32 + brw) * 128 + boff;
                ldsm4(bw, b[w][0], b[w][1], b[w][2], b[w][3]);
                ldsm4(bw + 16 * 128, b[w][4], b[w][5], b[w][6], b[w][7]);
            }
            const int PA[3] = {0, 1, 2}, PW[3] = {0, 1, 0};
#pragma unroll
            for (int p = 0; p < 3; p++) {
                uint32_t a[4][4];
#pragma unroll
                for (int mf = 0; mf < 4; mf++)
                    ldsm4(s0 + PA[p] * TILE + (wm * 64 + mf * 16 + arow) * 128 + aoff,
                          a[mf][0], a[mf][1], a[mf][2], a[mf][3]);
#pragma unroll
                for (int mf = 0; mf < 4; mf++)
#pragma unroll
                    for (int nf = 0; nf < 4; nf++)
                        mma16816(acc[mf][nf], a[mf], b[PW[p]][2 * nf], b[PW[p]][2 * nf + 1]);
            }
        }
        __syncthreads();
    }

    const int qr = lane >> 2, qc = (lane & 3) * 2;
#pragma unroll
    for (int mf = 0; mf < 4; mf++)
#pragma unroll
    for (int h2 = 0; h2 < 2; h2++) {
        const int row = brow + wm * 64 + mf * 16 + qr + 8 * h2;
#pragma unroll
        for (int nf = 0; nf < 4; nf++) {
            const int col = bcol + wn * 32 + nf * 8 + qc;
            const size_t ix = (size_t)row * N + col;
            float2 bb = *reinterpret_cast<const float2*>(bias + col);
            float m0  = acc[mf][nf][2 * h2 + 0] + bb.x;
            float m1v = acc[mf][nf][2 * h2 + 1] + bb.y;
            const bool sp0 = m0 > THRV, sp1 = m1v > THRV;
            *reinterpret_cast<float2*>(mem + ix) = make_float2(m0, m1v);
            uint32_t sv = (sp0 ? 0x1000u : 0u) | (sp1 ? 0x10000000u : 0u);
            *reinterpret_cast<uint32_t*>(spk + ix) = sv;
        }
    }
}

// ---------------------------------------------------------------------------
// Splits + readout
// ---------------------------------------------------------------------------
__global__ void __launch_bounds__(256)
split_w(const float* __restrict__ w, __half* __restrict__ hS,
        __half* __restrict__ lS, __half* __restrict__ hU, int n, int mkU)
{
    for (int i = blockIdx.x * 256 + threadIdx.x; i < n; i += gridDim.x * 256) {
        float v = w[i] * 2048.0f;
        __half h = __float2half_rn(v);
        float r = v - __half2float(h);
        hS[i] = h;
        lS[i] = __float2half_rn(r);
        if (mkU) hU[i] = __float2half_rn(__half2float(h) * (1.0f / 2048.0f));
    }
}

__global__ void __launch_bounds__(256)
split_x(const float* __restrict__ x, __half* __restrict__ xh,
        __half* __restrict__ xl, __half* __restrict__ xhs, int n)
{
    for (int i = blockIdx.x * 256 + threadIdx.x; i < n; i += gridDim.x * 256) {
        float v = x[i];
        __half h = __float2half_rn(v);
        float r = v - __half2float(h);
        xh[i] = h;
        xl[i] = __float2half_rn(r);
        xhs[i] = __float2half_rn(__half2float(h) * (1.0f / 2048.0f));
    }
}

__global__ void __launch_bounds__(256)
snn_readout(const float* __restrict__ spk_sum, const float* __restrict__ Wo,
            const float* __restrict__ bo, float* __restrict__ out)
{
    const int c  = threadIdx.x & 63;
    const int r4 = threadIdx.x >> 6;
    const size_t b = (size_t)blockIdx.x * 4 + r4;
    const float* s = spk_sum + b * DIM_H2;
    const float* w = Wo + (size_t)c * DIM_H2;
    float acc = 0.0f;
#pragma unroll 4
    for (int k = 0; k < DIM_H2; k += 4) {
        float4 sv = *reinterpret_cast<const float4*>(s + k);
        float4 wv = *reinterpret_cast<const float4*>(w + k);
        acc = fmaf(sv.x, wv.x, acc);
        acc = fmaf(sv.y, wv.y, acc);
        acc = fmaf(sv.z, wv.z, acc);
        acc = fmaf(sv.w, wv.w, acc);
    }
    out[b * DIM_C + c] = acc * (1.0f / (float)NUM_STEPS) + bo[c];
}

// ---------------------------------------------------------------------------
extern "C" void kernel_launch(void* const* d_in, const int* in_sizes, int n_in,
                              void* d_out, int out_size)
{
    const float* x  = (const float*)d_in[0];
    const float* W1 = (const float*)d_in[1];
    const float* b1 = (const float*)d_in[2];
    const float* W2 = (const float*)d_in[3];
    const float* b2 = (const float*)d_in[4];
    const float* Wo = (const float*)d_in[5];
    const float* bo = (const float*)d_in[6];
    float* out = (float*)d_out;

    auto sym = [](const void* s) { void* p; cudaGetSymbolAddress(&p, s); return p; };
    float*  m1   = (float*)sym(g_m1);
    float*  m2   = (float*)sym(g_m2);
    float*  spk  = (float*)sym(g_spk);
    __half* s1   = (__half*)sym(g_s1);
    __half* s2   = (__half*)sym(g_s2);
    __half* w1h  = (__half*)sym(g_w1h);
    __half* w1l  = (__half*)sym(g_w1l);
    __half* w1hu = (__half*)sym(g_w1hu);
    __half* w2h  = (__half*)sym(g_w2h);
    __half* w2l  = (__half*)sym(g_w2l);
    __half* xh   = (__half*)sym(g_xh);
    __half* xl   = (__half*)sym(g_xl);
    __half* xhs  = (__half*)sym(g_xhs);

    constexpr int SM_MAIN = 2 * (16384 + 2 * 32768);   // 163840 B
    constexpr int SM_TZ   = 2 * 5 * 16384;             // 163840 B
    cudaFuncSetAttribute(snn_tz,                 cudaFuncAttributeMaxDynamicSharedMemorySize, SM_TZ);
    cudaFuncSetAttribute(snn_main<true,  true >, cudaFuncAttributeMaxDynamicSharedMemorySize, SM_MAIN);
    cudaFuncSetAttribute(snn_main<false, false>, cudaFuncAttributeMaxDynamicSharedMemorySize, SM_MAIN);
    cudaFuncSetAttribute(snn_main<false, true >, cudaFuncAttributeMaxDynamicSharedMemorySize, SM_MAIN);

    split_w<<<2048, 256>>>(W1, w1h, w1l, w1hu, DIM_H1 * DIM_D, 1);
    split_w<<<2048, 256>>>(W2, w2h, w2l, nullptr, DIM_H2 * DIM_H1, 0);
    split_x<<<2048, 256>>>(x, xh, xl, xhs, BATCH * DIM_D);

    dim3 blk(256);
    dim3 gtz(DIM_H1 / 128, BATCH / 128);   // (16, 32)
    dim3 g1(DIM_H1 / 256, BATCH / 128);    // (8, 32)  = 256 CTAs
    dim3 g2(DIM_H2 / 256, BATCH / 128);    // (4, 32)  = 128 CTAs

    // t = 0 (mem starts at zero)
    snn_tz<<<gtz, blk, SM_TZ>>>(xh, xhs, xl, w1hu, w1l, b1, m1, s1, DIM_H1, DIM_D);
    snn_main<true, true><<<g2, blk, SM_MAIN>>>(
        s1, w2h, w2l, b2, m2, s2, spk, DIM_H2, DIM_H1);

    for (int t = 1; t < NUM_STEPS; t++) {
        snn_main<false, false><<<g1, blk, SM_MAIN>>>(
            s2, w1h, w1l, b1, m1, s1, nullptr, DIM_H1, DIM_D);
        snn_main<false, true><<<g2, blk, SM_MAIN>>>(
            s1, w2h, w2l, b2, m2, s2, spk, DIM_H2, DIM_H1);
    }

    snn_readout<<<BATCH / 4, blk>>>(spk, Wo, bo, out);
}